// round 12
// baseline (speedup 1.0000x reference)
#include <cuda_runtime.h>
#include <cuda_bf16.h>

// WeightedNHotEncodingLayer: out[row, ids[k]] += w[k] for k in row's CSR range.
// Output (16384 x 8192 fp32 = 512MB) dominates: write it exactly once.
//
// R2 vs R11 (measured): smem traffic is NOT the limiter (identical DRAM 70%,
// identical dur with and without full-row zero/readback). Remaining gap to the
// write roofline attributed to wave structure: 16384 CTAs ~= 18 waves, ~2360cyc
// per transition ~= 20us, plus per-CTA prologue amortized over only 32KB.
// This version: each CTA processes R=8 consecutive rows in-place (one
// srow+bitmap buffer, 3 barriers/row). Grid 2048, waves ~2.3. Store pattern
// per row unchanged (slot-major float4, measured DRAM-good).

#define MAX_ROWS 32768
#define ROWS_PER_CTA 8
__device__ int g_row_offsets[MAX_ROWS];

__global__ void __launch_bounds__(1024)
scan_row_lengths(const int* __restrict__ lens,
                 int* __restrict__ offs, int n) {
    __shared__ int partial[1024];
    const int t = threadIdx.x;
    const int items = (n + 1023) >> 10;
    const int base = t * items;

    int s = 0;
    if ((items & 3) == 0 && base + items <= n) {
        const int4* l4 = reinterpret_cast<const int4*>(lens + base);
        #pragma unroll 4
        for (int j = 0; j < items / 4; j++) {
            int4 v = __ldg(&l4[j]);
            s += v.x + v.y + v.z + v.w;
        }
    } else {
        for (int j = 0; j < items; j++) {
            int i = base + j;
            if (i < n) s += lens[i];
        }
    }
    partial[t] = s;
    __syncthreads();
    #pragma unroll
    for (int d = 1; d < 1024; d <<= 1) {
        int v = (t >= d) ? partial[t - d] : 0;
        __syncthreads();
        partial[t] += v;
        __syncthreads();
    }
    int run = partial[t] - s;
    for (int j = 0; j < items; j++) {
        int i = base + j;
        if (i < n) {
            offs[i] = run;
            run += lens[i];
        }
    }
}

__global__ void __launch_bounds__(256)
nhot_rows_kernel(const int* __restrict__ ids,
                 const float* __restrict__ w,
                 const int* __restrict__ lens,
                 const int* __restrict__ offs,
                 float* __restrict__ out,
                 int nb, int nrows) {
    // dyn smem: [ srow: nb floats ][ bitmap: nb/32 uints ]
    extern __shared__ float srow[];
    unsigned* bitmap = reinterpret_cast<unsigned*>(srow + nb);

    const int t   = threadIdx.x;
    const int nb4 = nb >> 2;   // float4 slots (2048)
    const int nbw = nb >> 5;   // bitmap words (256)

    const int r0 = blockIdx.x * ROWS_PER_CTA;
    const int r1 = min(nrows, r0 + ROWS_PER_CTA);

    for (int row = r0; row < r1; ++row) {
        const int len   = __ldg(&lens[row]);
        const int start = __ldg(&offs[row]);

        // Phase 1: zero bitmap; zero only the touched srow entries.
        for (int i = t; i < nbw; i += 256) bitmap[i] = 0u;
        for (int j = t; j < len; j += 256) {
            int id = __ldg(&ids[start + j]);
            srow[id] = 0.f;                // duplicate plain stores of 0: benign
        }
        __syncthreads();

        // Phase 2: accumulate (handles duplicate ids) and mark bitmap.
        for (int j = t; j < len; j += 256) {
            int id  = __ldg(&ids[start + j]);
            float v = __ldg(&w[start + j]);
            atomicAdd(&srow[id], v);
            atomicOr(&bitmap[id >> 5], 1u << (id & 31));
        }
        __syncthreads();

        // Phase 3 (slot-major, coalesced): thread t stores slots t, t+256, ...
        // Lane-consecutive float4 -> fully coalesced. Untouched slots emit a
        // register zero with no srow read.
        float4* o4 = reinterpret_cast<float4*>(out + (size_t)row * nb);
        #pragma unroll 8
        for (int i = t; i < nb4; i += 256) {
            unsigned wbits = bitmap[i >> 3];             // word covers 8 slots
            unsigned nib   = (wbits >> ((i & 7) << 2)) & 0xFu;
            float4 v = make_float4(0.f, 0.f, 0.f, 0.f);
            if (nib) {
                int b = i << 2;
                if (nib & 1u) v.x = srow[b + 0];
                if (nib & 2u) v.y = srow[b + 1];
                if (nib & 4u) v.z = srow[b + 2];
                if (nib & 8u) v.w = srow[b + 3];
            }
            __stcs(&o4[i], v);
        }

        // Safe buffer reuse: all LDS results are in registers before STG issue;
        // this barrier only orders store-ISSUE vs next row's smem writes.
        __syncthreads();
    }
}

extern "C" void kernel_launch(void* const* d_in, const int* in_sizes, int n_in,
                              void* d_out, int out_size) {
    const int*   ids  = (const int*)d_in[0];     // values (NNZ,1) int32
    const int*   lens = (const int*)d_in[1];     // row_lengths (B,1) int32
    const float* w    = (const float*)d_in[2];   // weight_values (NNZ,1) f32
    // d_in[3] = weight_row_lengths (identical; unused)
    float* out = (float*)d_out;

    const int B  = in_sizes[1];            // 16384 rows
    const int nb = out_size / B;           // 8192 buckets

    int* offs;
    cudaGetSymbolAddress((void**)&offs, g_row_offsets);

    scan_row_lengths<<<1, 1024>>>(lens, offs, B);

    const int grid = (B + ROWS_PER_CTA - 1) / ROWS_PER_CTA;   // 2048
    const size_t smem = (size_t)nb * sizeof(float) + (size_t)(nb >> 5) * sizeof(unsigned);
    nhot_rows_kernel<<<grid, 256, smem>>>(ids, w, lens, offs, out, nb, B);
}